// round 5
// baseline (speedup 1.0000x reference)
#include <cuda_runtime.h>
#include <cstdint>

// CenterLoss: BATCH=4096, FEAT_DIM=256, NUM_CLASSES=8192
#define BATCH       4096
#define FEAT_DIM    256
#define NUM_CLASSES 8192
#define NBLOCKS     512
#define NTHREADS    512          // 16 warps/CTA; 8 samples/CTA; 2 warps/sample
#define SCALE       268435456.0  // 2^28 fixed-point scale

__device__ unsigned long long g_part[NBLOCKS];
__device__ unsigned int       g_count = 0u;

__global__ void __launch_bounds__(NTHREADS, 2) center_loss_fused(
    const float* __restrict__ x,
    const void*  __restrict__ labels_raw,
    const float* __restrict__ centers,
    float*       __restrict__ out)
{
    const int lane = threadIdx.x & 31;
    const int warp = threadIdx.x >> 5;        // 0..15
    const int h    = warp & 1;                // half of the row
    const int s    = blockIdx.x * 8 + (warp >> 1);   // sample id 0..4095

    // ---- dtype probe: words 0..7 (one 128B line, in-bounds both layouts,
    // warp-uniform -> no ballot). i64 => odd words all zero.
    const int4* lw = (const int4*)labels_raw;
    int4 q0 = lw[0];
    int4 q1 = lw[1];

    // ---- speculative i32 label (word s: in-bounds under both layouts)
    int li32 = ((const int*)labels_raw)[s];

    // ---- x half-row load (row = 64 float4; this warp takes 32)
    float4 a = ((const float4*)(x + (size_t)s * FEAT_DIM))[32 * h + lane];

    const bool is_i64 = ((q0.y | q0.w | q1.y | q1.w) == 0);
    int lbl = is_i64 ? (int)((const long long*)labels_raw)[s] : li32;

    float4 b = ((const float4*)(centers + (size_t)lbl * FEAT_DIM))[32 * h + lane];

    float acc = 0.0f, d;
    d = a.x - b.x; acc = fmaf(d, d, acc);
    d = a.y - b.y; acc = fmaf(d, d, acc);
    d = a.z - b.z; acc = fmaf(d, d, acc);
    d = a.w - b.w; acc = fmaf(d, d, acc);

#pragma unroll
    for (int o = 16; o > 0; o >>= 1)
        acc += __shfl_xor_sync(0xFFFFFFFFu, acc, o);

    __shared__ float sh[16];
    if (lane == 0) sh[warp] = acc;
    __syncthreads();

    if (warp == 0) {
        // lanes 0..15 hold the 16 half-sums; pair (2i, 2i+1) = sample i.
        float w = (lane < 16) ? sh[lane] : 0.0f;
        w += __shfl_xor_sync(0xFFFFFFFFu, w, 1);   // both lanes of pair hold sum
        unsigned long long p = 0ull;
        if (lane < 16 && (lane & 1) == 0) {
            float v = fminf(fmaxf(w, 1e-12f), 1e12f);
            p = (unsigned long long)((double)v * SCALE);
        }
#pragma unroll
        for (int o = 16; o > 0; o >>= 1)
            p += __shfl_xor_sync(0xFFFFFFFFu, p, o);

        unsigned int old = 0u;
        if (lane == 0) {
            g_part[blockIdx.x] = p;
            __threadfence();
            old = atomicAdd(&g_count, 1u);
        }
        old = __shfl_sync(0xFFFFFFFFu, old, 0);

        if (old == NBLOCKS - 1) {
            __threadfence();   // all g_part stores visible
            unsigned long long t = 0ull;
#pragma unroll
            for (int i = 0; i < NBLOCKS / 32; i++)
                t += g_part[lane + 32 * i];
#pragma unroll
            for (int o = 16; o > 0; o >>= 1)
                t += __shfl_xor_sync(0xFFFFFFFFu, t, o);
            if (lane == 0) {
                double loss = ((double)t / SCALE) / (double)BATCH
                            + (double)(NUM_CLASSES - 1) * 1e-12;
                out[0] = (float)loss;
                g_count = 0u;   // reset for next graph replay
            }
        }
    }
}

extern "C" void kernel_launch(void* const* d_in, const int* in_sizes, int n_in,
                              void* d_out, int out_size)
{
    const float* x       = (const float*)d_in[0];
    const void*  labels  = d_in[1];
    const float* centers = (const float*)d_in[2];
    float*       out     = (float*)d_out;
    (void)in_sizes; (void)n_in; (void)out_size;

    center_loss_fused<<<NBLOCKS, NTHREADS>>>(x, labels, centers, out);
}

// round 6
// speedup vs baseline: 1.4649x; 1.4649x over previous
#include <cuda_runtime.h>
#include <cstdint>

// CenterLoss: BATCH=4096, FEAT_DIM=256, NUM_CLASSES=8192
#define BATCH       4096
#define FEAT_DIM    256
#define NUM_CLASSES 8192
#define NBLOCKS     512
#define NTHREADS    256          // 8 warps/CTA, warp-per-sample (R2 config)
#define SCALE       268435456.0  // 2^28 fixed-point scale

__device__ unsigned long long g_part[NBLOCKS];
__device__ unsigned int       g_count = 0u;

__global__ void __launch_bounds__(NTHREADS) center_loss_fused(
    const float* __restrict__ x,
    const void*  __restrict__ labels_raw,
    const float* __restrict__ centers,
    float*       __restrict__ out)
{
    const int lane = threadIdx.x & 31;
    const int warp = threadIdx.x >> 5;            // 0..7
    const int s    = blockIdx.x * 8 + warp;       // sample id 0..4095

    // ---- ALL label-related loads issued concurrently, no ballot, no branch.
    // Probe: words 0..7 (one 128B line, warp-uniform addr -> broadcast).
    // i64 layout => odd words all zero (labels < 8192).
    // False-i64 under i32 layout: labels[1],[3],[5],[7] all zero, p = 8192^-4.
    const int4 q0 = ((const int4*)labels_raw)[0];
    const int4 q1 = ((const int4*)labels_raw)[1];
    // Speculative i32 label: word s (in-bounds both layouts: i32 has 4096
    // words, i64 has 8192).
    const int       li32 = ((const int*)labels_raw)[s];
    // Speculative i64 label: words 2s,2s+1. Under i32 layout this reads
    // words up to 8191 of a 4096-word buffer... NOT safe. Guard: only the
    // first half of samples can pre-load i64 unconditionally; instead read
    // word 2s only when it is in-bounds for i32 too (2s <= 4095 <=> s<2048).
    // To keep it branch-free AND safe for all s, load from a clamped address
    // and patch: addresses 2s,2s+1 are in-bounds iff layout is i64; we fold
    // the select into the address instead of the data.
    // -> compute predicate first from q0/q1 (registers, ~20 cyc), then one
    //    uniform load from the correct address. Chain: probe -> label -> center.
    const bool is_i64 = ((q0.y | q0.w | q1.y | q1.w) == 0);

    int lbl;
    if (is_i64) lbl = (int)((const long long*)labels_raw)[s];
    else        lbl = li32;

    // ---- x loads: independent, issued before label resolves.
    const float4* xr = (const float4*)(x + (size_t)s * FEAT_DIM);
    float4 a0 = xr[lane];
    float4 a1 = xr[lane + 32];

    const float4* cr = (const float4*)(centers + (size_t)lbl * FEAT_DIM);
    float4 b0 = cr[lane];
    float4 b1 = cr[lane + 32];

    float acc = 0.0f, d;
    d = a0.x - b0.x; acc = fmaf(d, d, acc);
    d = a0.y - b0.y; acc = fmaf(d, d, acc);
    d = a0.z - b0.z; acc = fmaf(d, d, acc);
    d = a0.w - b0.w; acc = fmaf(d, d, acc);
    d = a1.x - b1.x; acc = fmaf(d, d, acc);
    d = a1.y - b1.y; acc = fmaf(d, d, acc);
    d = a1.z - b1.z; acc = fmaf(d, d, acc);
    d = a1.w - b1.w; acc = fmaf(d, d, acc);

#pragma unroll
    for (int o = 16; o > 0; o >>= 1)
        acc += __shfl_xor_sync(0xFFFFFFFFu, acc, o);

    // ---- per-CTA tail (clamp per sample, fixed-point, deterministic)
    __shared__ float sh[8];
    if (lane == 0) sh[warp] = fminf(fmaxf(acc, 1e-12f), 1e12f);
    __syncthreads();

    if (warp == 0) {
        unsigned long long p = 0ull;
        if (lane < 8)
            p = (unsigned long long)((double)sh[lane] * SCALE);
#pragma unroll
        for (int o = 4; o > 0; o >>= 1)
            p += __shfl_xor_sync(0xFFFFFFFFu, p, o);

        unsigned int old = 0u;
        if (lane == 0) {
            g_part[blockIdx.x] = p;
            __threadfence();
            old = atomicAdd(&g_count, 1u);
        }
        old = __shfl_sync(0xFFFFFFFFu, old, 0);

        if (old == NBLOCKS - 1) {
            __threadfence();   // all g_part stores visible
            unsigned long long t = 0ull;
#pragma unroll
            for (int i = 0; i < NBLOCKS / 32; i++)
                t += g_part[lane + 32 * i];
#pragma unroll
            for (int o = 16; o > 0; o >>= 1)
                t += __shfl_xor_sync(0xFFFFFFFFu, t, o);
            if (lane == 0) {
                double loss = ((double)t / SCALE) / (double)BATCH
                            + (double)(NUM_CLASSES - 1) * 1e-12;
                out[0] = (float)loss;
                g_count = 0u;   // reset for next graph replay
            }
        }
    }
}

extern "C" void kernel_launch(void* const* d_in, const int* in_sizes, int n_in,
                              void* d_out, int out_size)
{
    const float* x       = (const float*)d_in[0];
    const void*  labels  = d_in[1];
    const float* centers = (const float*)d_in[2];
    float*       out     = (float*)d_out;
    (void)in_sizes; (void)n_in; (void)out_size;

    center_loss_fused<<<NBLOCKS, NTHREADS>>>(x, labels, centers, out);
}

// round 7
// speedup vs baseline: 1.9179x; 1.3092x over previous
#include <cuda_runtime.h>
#include <cstdint>

// CenterLoss: BATCH=4096, FEAT_DIM=256, NUM_CLASSES=8192
#define BATCH       4096
#define FEAT_DIM    256
#define NUM_CLASSES 8192
#define NBLOCKS     512
#define NTHREADS    256            // 8 warps/CTA, warp-per-sample
#define SCALE       16777216.0     // 2^24 fixed-point scale
#define CNT_SHIFT   50             // count lives in bits [50..63]
#define SUM_MASK    ((1ull << CNT_SHIFT) - 1ull)

// Single packed accumulator: bits [0,50) = fixed-point sum, bits [50,64) = CTA count.
__device__ unsigned long long g_acc = 0ull;

__global__ void __launch_bounds__(NTHREADS) center_loss_fused(
    const float* __restrict__ x,
    const void*  __restrict__ labels_raw,
    const float* __restrict__ centers,
    float*       __restrict__ out)
{
    const int lane = threadIdx.x & 31;
    const int warp = threadIdx.x >> 5;            // 0..7
    const int s    = blockIdx.x * 8 + warp;       // sample id 0..4095

    // ---- dtype probe: words 0..7 (one 128B line, warp-uniform -> broadcast,
    // concurrent with the label + x loads below). i64 => odd words all zero.
    // False-i64 under i32: labels[1,3,5,7]==0, p = 8192^-4 ~ 2e-16.
    const int4 q0 = ((const int4*)labels_raw)[0];
    const int4 q1 = ((const int4*)labels_raw)[1];

    // Speculative i32 label: word s (in-bounds under both layouts).
    const int li32 = ((const int*)labels_raw)[s];

    // x loads: independent of labels, issued before the predicate resolves.
    const float4* xr = (const float4*)(x + (size_t)s * FEAT_DIM);
    float4 a0 = xr[lane];
    float4 a1 = xr[lane + 32];

    const bool is_i64 = ((q0.y | q0.w | q1.y | q1.w) == 0);
    int lbl;
    if (is_i64) lbl = (int)((const long long*)labels_raw)[s];
    else        lbl = li32;

    const float4* cr = (const float4*)(centers + (size_t)lbl * FEAT_DIM);
    float4 b0 = cr[lane];
    float4 b1 = cr[lane + 32];

    float acc = 0.0f, d;
    d = a0.x - b0.x; acc = fmaf(d, d, acc);
    d = a0.y - b0.y; acc = fmaf(d, d, acc);
    d = a0.z - b0.z; acc = fmaf(d, d, acc);
    d = a0.w - b0.w; acc = fmaf(d, d, acc);
    d = a1.x - b1.x; acc = fmaf(d, d, acc);
    d = a1.y - b1.y; acc = fmaf(d, d, acc);
    d = a1.z - b1.z; acc = fmaf(d, d, acc);
    d = a1.w - b1.w; acc = fmaf(d, d, acc);

#pragma unroll
    for (int o = 16; o > 0; o >>= 1)
        acc += __shfl_xor_sync(0xFFFFFFFFu, acc, o);

    // ---- per-CTA combine (clamp per sample, fixed point, deterministic)
    __shared__ float sh[8];
    if (lane == 0) sh[warp] = fminf(fmaxf(acc, 1e-12f), 1e12f);
    __syncthreads();

    if (warp == 0) {
        unsigned long long p = 0ull;
        if (lane < 8)
            p = (unsigned long long)((double)sh[lane] * SCALE);
#pragma unroll
        for (int o = 4; o > 0; o >>= 1)
            p += __shfl_xor_sync(0xFFFFFFFFu, p, o);

        if (lane == 0) {
            // One packed atomic: add partial sum and bump count.
            unsigned long long old =
                atomicAdd(&g_acc, p + (1ull << CNT_SHIFT));
            if ((old >> CNT_SHIFT) == NBLOCKS - 1) {
                // Last CTA: prior sum + own partial = total. No extra loads.
                unsigned long long total = (old & SUM_MASK) + p;
                double loss = ((double)total / SCALE) / (double)BATCH
                            + (double)(NUM_CLASSES - 1) * 1e-12;
                out[0] = (float)loss;
                g_acc = 0ull;   // reset for next graph replay
            }
        }
    }
}

extern "C" void kernel_launch(void* const* d_in, const int* in_sizes, int n_in,
                              void* d_out, int out_size)
{
    const float* x       = (const float*)d_in[0];
    const void*  labels  = d_in[1];
    const float* centers = (const float*)d_in[2];
    float*       out     = (float*)d_out;
    (void)in_sizes; (void)n_in; (void)out_size;

    center_loss_fused<<<NBLOCKS, NTHREADS>>>(x, labels, centers, out);
}